// round 2
// baseline (speedup 1.0000x reference)
#include <cuda_runtime.h>

// Unitary gate on wires {5,13} of a 26-wire register (target bits 20 and 12).
// out[b + off] = U[4x4] @ x[b + off], off ∈ {0, 2^12, 2^20, 2^20+2^12}.
//
// DRAM-bound streaming kernel: 512 MB total traffic.
// R2: streaming cache hints (evict-first) + 2x float4 per stream per thread
// (MLP=8) to close the DRAM-idle gap (80.8% active in R1).

static constexpr unsigned REST    = 1u << 24;   // rest-index count
static constexpr unsigned THREADS = REST / 8;   // 8 consecutive rest positions / thread

static constexpr unsigned OFF12_V4 = (1u << 12) >> 2;  // stream offsets in float4 units
static constexpr unsigned OFF20_V4 = (1u << 20) >> 2;

__device__ __forceinline__ float4 ldcs4(const float4* p) { return __ldcs(p); }
__device__ __forceinline__ void   stcs4(float4* p, float4 v) { __stcs(p, v); }

__global__ __launch_bounds__(256)
void unitary_gate_kernel(const float4* __restrict__ x4,
                         const float*  __restrict__ U,
                         float4*       __restrict__ o4)
{
    unsigned r  = blockIdx.x * blockDim.x + threadIdx.x;   // 0 .. 2^21-1
    unsigned rr = r << 3;                                  // rest index (multiple of 8)

    // Insert zero bits at positions 12 and 20 of the flat amplitude index:
    //   rr bits [0..11]  -> base bits [0..11]
    //   rr bits [12..18] -> base bits [13..19]
    //   rr bits [19..23] -> base bits [21..25]
    unsigned base = (rr & 0x00000FFFu)
                  | ((rr & 0x0007F000u) << 1)
                  | ((rr & 0x00F80000u) << 2);
    unsigned i0 = base >> 2;  // float4 index (base is a multiple of 8)

    // Gate matrix (broadcast, L2-resident). Keep default caching for U.
    float u00 = __ldg(U +  0), u01 = __ldg(U +  1), u02 = __ldg(U +  2), u03 = __ldg(U +  3);
    float u10 = __ldg(U +  4), u11 = __ldg(U +  5), u12 = __ldg(U +  6), u13 = __ldg(U +  7);
    float u20 = __ldg(U +  8), u21 = __ldg(U +  9), u22 = __ldg(U + 10), u23 = __ldg(U + 11);
    float u30 = __ldg(U + 12), u31 = __ldg(U + 13), u32 = __ldg(U + 14), u33 = __ldg(U + 15);

    // Front-batched loads: 8 independent 16B streaming loads (MLP=8).
    float4 a0 = ldcs4(x4 + i0);
    float4 b0 = ldcs4(x4 + i0 + 1);
    float4 a1 = ldcs4(x4 + i0 + OFF12_V4);
    float4 b1 = ldcs4(x4 + i0 + OFF12_V4 + 1);
    float4 a2 = ldcs4(x4 + i0 + OFF20_V4);
    float4 b2 = ldcs4(x4 + i0 + OFF20_V4 + 1);
    float4 a3 = ldcs4(x4 + i0 + OFF20_V4 + OFF12_V4);
    float4 b3 = ldcs4(x4 + i0 + OFF20_V4 + OFF12_V4 + 1);

    float4 d;

    // row 0
    d.x = u00*a0.x + u01*a1.x + u02*a2.x + u03*a3.x;
    d.y = u00*a0.y + u01*a1.y + u02*a2.y + u03*a3.y;
    d.z = u00*a0.z + u01*a1.z + u02*a2.z + u03*a3.z;
    d.w = u00*a0.w + u01*a1.w + u02*a2.w + u03*a3.w;
    stcs4(o4 + i0, d);
    d.x = u00*b0.x + u01*b1.x + u02*b2.x + u03*b3.x;
    d.y = u00*b0.y + u01*b1.y + u02*b2.y + u03*b3.y;
    d.z = u00*b0.z + u01*b1.z + u02*b2.z + u03*b3.z;
    d.w = u00*b0.w + u01*b1.w + u02*b2.w + u03*b3.w;
    stcs4(o4 + i0 + 1, d);

    // row 1
    d.x = u10*a0.x + u11*a1.x + u12*a2.x + u13*a3.x;
    d.y = u10*a0.y + u11*a1.y + u12*a2.y + u13*a3.y;
    d.z = u10*a0.z + u11*a1.z + u12*a2.z + u13*a3.z;
    d.w = u10*a0.w + u11*a1.w + u12*a2.w + u13*a3.w;
    stcs4(o4 + i0 + OFF12_V4, d);
    d.x = u10*b0.x + u11*b1.x + u12*b2.x + u13*b3.x;
    d.y = u10*b0.y + u11*b1.y + u12*b2.y + u13*b3.y;
    d.z = u10*b0.z + u11*b1.z + u12*b2.z + u13*b3.z;
    d.w = u10*b0.w + u11*b1.w + u12*b2.w + u13*b3.w;
    stcs4(o4 + i0 + OFF12_V4 + 1, d);

    // row 2
    d.x = u20*a0.x + u21*a1.x + u22*a2.x + u23*a3.x;
    d.y = u20*a0.y + u21*a1.y + u22*a2.y + u23*a3.y;
    d.z = u20*a0.z + u21*a1.z + u22*a2.z + u23*a3.z;
    d.w = u20*a0.w + u21*a1.w + u22*a2.w + u23*a3.w;
    stcs4(o4 + i0 + OFF20_V4, d);
    d.x = u20*b0.x + u21*b1.x + u22*b2.x + u23*b3.x;
    d.y = u20*b0.y + u21*b1.y + u22*b2.y + u23*b3.y;
    d.z = u20*b0.z + u21*b1.z + u22*b2.z + u23*b3.z;
    d.w = u20*b0.w + u21*b1.w + u22*b2.w + u23*b3.w;
    stcs4(o4 + i0 + OFF20_V4 + 1, d);

    // row 3
    d.x = u30*a0.x + u31*a1.x + u32*a2.x + u33*a3.x;
    d.y = u30*a0.y + u31*a1.y + u32*a2.y + u33*a3.y;
    d.z = u30*a0.z + u31*a1.z + u32*a2.z + u33*a3.z;
    d.w = u30*a0.w + u31*a1.w + u32*a2.w + u33*a3.w;
    stcs4(o4 + i0 + OFF20_V4 + OFF12_V4, d);
    d.x = u30*b0.x + u31*b1.x + u32*b2.x + u33*b3.x;
    d.y = u30*b0.y + u31*b1.y + u32*b2.y + u33*b3.y;
    d.z = u30*b0.z + u31*b1.z + u32*b2.z + u33*b3.z;
    d.w = u30*b0.w + u31*b1.w + u32*b2.w + u33*b3.w;
    stcs4(o4 + i0 + OFF20_V4 + OFF12_V4 + 1, d);
}

extern "C" void kernel_launch(void* const* d_in, const int* in_sizes, int n_in,
                              void* d_out, int out_size)
{
    const float* x = (const float*)d_in[0];
    const float* U = (const float*)d_in[1];
    if (n_in >= 2 && in_sizes[0] == 16) {  // defensive: swapped order
        U = (const float*)d_in[0];
        x = (const float*)d_in[1];
    }
    float* out = (float*)d_out;

    const unsigned threads = 256;
    const unsigned blocks  = THREADS / threads;  // 8192
    unitary_gate_kernel<<<blocks, threads>>>(
        (const float4*)x, U, (float4*)out);
}

// round 3
// speedup vs baseline: 1.0789x; 1.0789x over previous
#include <cuda_runtime.h>

// Unitary gate on wires {5,13} of a 26-wire register (target bits 20 and 12).
// out[b + off] = U[4x4] @ x[b + off], off ∈ {0, 2^12, 2^20, 2^20+2^12}.
//
// DRAM-bound streaming kernel, 512 MB total traffic.
// R3 = R1 structure (4 x float4 / thread, 32 regs, high occupancy) + streaming
// cache hints ONLY. R2 showed per-thread unrolling destroys occupancy (59 regs,
// 40% occ, DRAM 70%) — reverted.

static constexpr unsigned REST    = 1u << 24;   // rest-index count
static constexpr unsigned THREADS = REST / 4;   // 4 consecutive rest positions / thread

static constexpr unsigned OFF12_V4 = (1u << 12) >> 2;  // stream offsets in float4 units
static constexpr unsigned OFF20_V4 = (1u << 20) >> 2;

__global__ __launch_bounds__(256)
void unitary_gate_kernel(const float4* __restrict__ x4,
                         const float*  __restrict__ U,
                         float4*       __restrict__ o4)
{
    unsigned r  = blockIdx.x * blockDim.x + threadIdx.x;   // 0 .. 2^22-1
    unsigned rr = r << 2;                                  // rest index (multiple of 4)

    // Insert zero bits at positions 12 and 20 of the flat amplitude index:
    //   rr bits [0..11]  -> base bits [0..11]
    //   rr bits [12..18] -> base bits [13..19]
    //   rr bits [19..23] -> base bits [21..25]
    unsigned base = (rr & 0x00000FFFu)
                  | ((rr & 0x0007F000u) << 1)
                  | ((rr & 0x00F80000u) << 2);
    unsigned i0 = base >> 2;  // float4 index (base is a multiple of 4)

    // Gate matrix (broadcast, L2-resident; default caching).
    float u00 = __ldg(U +  0), u01 = __ldg(U +  1), u02 = __ldg(U +  2), u03 = __ldg(U +  3);
    float u10 = __ldg(U +  4), u11 = __ldg(U +  5), u12 = __ldg(U +  6), u13 = __ldg(U +  7);
    float u20 = __ldg(U +  8), u21 = __ldg(U +  9), u22 = __ldg(U + 10), u23 = __ldg(U + 11);
    float u30 = __ldg(U + 12), u31 = __ldg(U + 13), u32 = __ldg(U + 14), u33 = __ldg(U + 15);

    // Front-batched streaming loads (MLP=4, evict-first).
    float4 s0 = __ldcs(x4 + i0);
    float4 s1 = __ldcs(x4 + i0 + OFF12_V4);
    float4 s2 = __ldcs(x4 + i0 + OFF20_V4);
    float4 s3 = __ldcs(x4 + i0 + OFF20_V4 + OFF12_V4);

    float4 d0, d1, d2, d3;
    d0.x = u00*s0.x + u01*s1.x + u02*s2.x + u03*s3.x;
    d0.y = u00*s0.y + u01*s1.y + u02*s2.y + u03*s3.y;
    d0.z = u00*s0.z + u01*s1.z + u02*s2.z + u03*s3.z;
    d0.w = u00*s0.w + u01*s1.w + u02*s2.w + u03*s3.w;

    d1.x = u10*s0.x + u11*s1.x + u12*s2.x + u13*s3.x;
    d1.y = u10*s0.y + u11*s1.y + u12*s2.y + u13*s3.y;
    d1.z = u10*s0.z + u11*s1.z + u12*s2.z + u13*s3.z;
    d1.w = u10*s0.w + u11*s1.w + u12*s2.w + u13*s3.w;

    d2.x = u20*s0.x + u21*s1.x + u22*s2.x + u23*s3.x;
    d2.y = u20*s0.y + u21*s1.y + u22*s2.y + u23*s3.y;
    d2.z = u20*s0.z + u21*s1.z + u22*s2.z + u23*s3.z;
    d2.w = u20*s0.w + u21*s1.w + u22*s2.w + u23*s3.w;

    d3.x = u30*s0.x + u31*s1.x + u32*s2.x + u33*s3.x;
    d3.y = u30*s0.y + u31*s1.y + u32*s2.y + u33*s3.y;
    d3.z = u30*s0.z + u31*s1.z + u32*s2.z + u33*s3.z;
    d3.w = u30*s0.w + u31*s1.w + u32*s2.w + u33*s3.w;

    __stcs(o4 + i0,                       d0);
    __stcs(o4 + i0 + OFF12_V4,            d1);
    __stcs(o4 + i0 + OFF20_V4,            d2);
    __stcs(o4 + i0 + OFF20_V4 + OFF12_V4, d3);
}

extern "C" void kernel_launch(void* const* d_in, const int* in_sizes, int n_in,
                              void* d_out, int out_size)
{
    const float* x = (const float*)d_in[0];
    const float* U = (const float*)d_in[1];
    if (n_in >= 2 && in_sizes[0] == 16) {  // defensive: swapped order
        U = (const float*)d_in[0];
        x = (const float*)d_in[1];
    }
    float* out = (float*)d_out;

    const unsigned threads = 256;
    const unsigned blocks  = THREADS / threads;  // 16384
    unitary_gate_kernel<<<blocks, threads>>>(
        (const float4*)x, U, (float4*)out);
}